// round 8
// baseline (speedup 1.0000x reference)
#include <cuda_runtime.h>

// 3-level db4 wavelet front-end, fully fused: one CTA per (b,c) row.
// R5: analysis/synthesis phase interleaving (6 barriers) + register-fused
// double-synthesis (2054 -> 4100 -> 8192 in one pass, no 4100 smem buffers).

#define NT 512
#define LEN0 8192
#define LEN1 4100
#define LEN2 2054
#define LEN3 1031

// ---- smem arena (floats); all offsets 16B-aligned ----
// P1 : read X[0,8192)        write A1[8192,12292) D1[12292,16392)
// P2 : read A1, D1(->gmem)   write A2[0,2056)     D2[2056,4112)
// P3 : read A2, D2(->gmem)   write D3[4112,5144)  A3[5144,6176)
// P4 : read D3, A3           write B1_1[8192,10248) B0_1[10248,12304)
// P5 : read B1_1, B0_1       write gmem only
#define ARENA    16392
#define OFF_X    0
#define OFF_A1   8192
#define OFF_D1   12292
#define OFF_A2   0
#define OFF_D2   2056
#define OFF_D3   4112
#define OFF_A3   5144
#define OFF_B1_1 8192
#define OFF_B0_1 10248

__constant__ float c_dec_lo[8] = {
    -0.0105974018f, 0.0328830117f, 0.0308413818f, -0.1870348117f,
    -0.0279837694f, 0.6308807679f, 0.7148465706f, 0.2303778133f};
__constant__ float c_dec_hi[8] = {
    -0.2303778133f, 0.7148465706f, -0.6308807679f, -0.0279837694f,
     0.1870348117f, 0.0308413818f, -0.0328830117f, -0.0105974018f};

// Synthesis polyphase taps (transpose conv, crop 7, T = 2L-8):
//   out[2u]   = e0*a[u]   + e1*a[u+1] + e2*a[u+2] + e3*a[u+3]
//   out[2u+1] = o0*a[u+1] + o1*a[u+2] + o2*a[u+3] + o3*a[u+4]
__constant__ float c_lo_e[4] = {-0.0105974018f, 0.0308413818f, -0.0279837694f, 0.7148465706f};
__constant__ float c_lo_o[4] = { 0.0328830117f, -0.1870348117f, 0.6308807679f, 0.2303778133f};
__constant__ float c_hi_e[4] = {-0.2303778133f, -0.6308807679f, 0.1870348117f, -0.0328830117f};
__constant__ float c_hi_o[4] = { 0.7148465706f, -0.0279837694f, 0.0308413818f, -0.0105974018f};

// ---------------- analysis: stride-2 correlation, reflect pad 7 ----------------
__device__ __forceinline__ void analysis_step(const float* __restrict__ in, int L,
                                              float* __restrict__ lo, float* __restrict__ hi,
                                              int Lout, int tid) {
    const int nchunk = (Lout + 3) >> 2;
    const int jhi = (L - 8) >> 3;
    const int twoLm2 = 2 * L - 2;
    for (int j = tid; j < nchunk; j += NT) {
        if (j >= 1 && j <= jhi) {
            const float4* in4 = reinterpret_cast<const float4*>(in) + (2 * j - 2);
            float v[16];
#pragma unroll
            for (int q = 0; q < 4; q++) {
                float4 t = in4[q];
                v[4 * q] = t.x; v[4 * q + 1] = t.y; v[4 * q + 2] = t.z; v[4 * q + 3] = t.w;
            }
            float slo[4], shi[4];
#pragma unroll
            for (int m = 0; m < 4; m++) {
                float sl = 0.f, sh = 0.f;
#pragma unroll
                for (int k = 0; k < 8; k++) {
                    float xv = v[2 * m + 1 + k];
                    sl = fmaf(xv, c_dec_lo[k], sl);
                    sh = fmaf(xv, c_dec_hi[k], sh);
                }
                slo[m] = sl; shi[m] = sh;
            }
            *reinterpret_cast<float4*>(lo + 4 * j) = make_float4(slo[0], slo[1], slo[2], slo[3]);
            *reinterpret_cast<float4*>(hi + 4 * j) = make_float4(shi[0], shi[1], shi[2], shi[3]);
        } else {
#pragma unroll
            for (int m = 0; m < 4; m++) {
                int o = 4 * j + m;
                if (o >= Lout) break;
                int base = 2 * o - 7;
                float sl = 0.f, sh = 0.f;
#pragma unroll
                for (int k = 0; k < 8; k++) {
                    int i = base + k;
                    i = i < 0 ? -i : i;
                    i = min(i, twoLm2 - i);
                    float xv = in[i];
                    sl = fmaf(xv, c_dec_lo[k], sl);
                    sh = fmaf(xv, c_dec_hi[k], sh);
                }
                lo[o] = sl;
                hi[o] = sh;
            }
        }
    }
}

// --------- single synthesis stage (smem or gmem out), chunk of 4 pairs ---------
__device__ __forceinline__ void synth_step(const float* __restrict__ a, int L,
                                           const float* __restrict__ wE, const float* __restrict__ wO,
                                           float* __restrict__ out, int tid) {
    const int halfT = L - 4;
    const int nchunk = (halfT + 3) >> 2;
    const float e0 = wE[0], e1 = wE[1], e2 = wE[2], e3 = wE[3];
    const float o0 = wO[0], o1 = wO[1], o2 = wO[2], o3 = wO[3];
    for (int j = tid; j < nchunk; j += NT) {
        const int u0 = 4 * j;
        if (u0 + 4 <= halfT) {
            const float4* a4 = reinterpret_cast<const float4*>(a + u0);
            float4 A = a4[0], B = a4[1];
            float v[8] = {A.x, A.y, A.z, A.w, B.x, B.y, B.z, B.w};
            float r[8];
#pragma unroll
            for (int m = 0; m < 4; m++) {
                r[2 * m]     = fmaf(e0, v[m],     fmaf(e1, v[m + 1], fmaf(e2, v[m + 2], e3 * v[m + 3])));
                r[2 * m + 1] = fmaf(o0, v[m + 1], fmaf(o1, v[m + 2], fmaf(o2, v[m + 3], o3 * v[m + 4])));
            }
            float4* o4 = reinterpret_cast<float4*>(out + 8 * j);
            o4[0] = make_float4(r[0], r[1], r[2], r[3]);
            o4[1] = make_float4(r[4], r[5], r[6], r[7]);
        } else {
            for (int u = u0; u < halfT; u++) {
                float a0 = a[u], a1 = a[u + 1], a2 = a[u + 2], a3 = a[u + 3], a4v = a[u + 4];
                out[2 * u]     = fmaf(e0, a0, fmaf(e1, a1, fmaf(e2, a2, e3 * a3)));
                out[2 * u + 1] = fmaf(o0, a1, fmaf(o1, a2, fmaf(o2, a3, o3 * a4v)));
            }
        }
    }
}

// ------ fused double synthesis: b(Lb) ->stageA-> mid(2Lb-8) ->stageB-> gmem ------
// Final halfT2 = 2*Lb - 12 pairs; chunk of 8 pairs reads b[4j..4j+11] and
// writes out[16j..16j+15]. For Lb=2054: halfT2=4096, 512 chunks exactly.
__device__ __forceinline__ void synth2_fused(const float* __restrict__ b, int Lb,
                                             const float* __restrict__ wAe, const float* __restrict__ wAo,
                                             const float* __restrict__ wBe, const float* __restrict__ wBo,
                                             float* __restrict__ outg, int tid) {
    const int halfT2 = 2 * Lb - 12;
    const int nchunk = halfT2 >> 3;      // exact for our sizes (4096/8)
    const float a0 = wAe[0], a1 = wAe[1], a2 = wAe[2], a3 = wAe[3];
    const float p0 = wAo[0], p1 = wAo[1], p2 = wAo[2], p3 = wAo[3];
    const float e0 = wBe[0], e1 = wBe[1], e2 = wBe[2], e3 = wBe[3];
    const float o0 = wBo[0], o1 = wBo[1], o2 = wBo[2], o3 = wBo[3];
    for (int j = tid; j < nchunk; j += NT) {
        const float4* b4 = reinterpret_cast<const float4*>(b + 4 * j);
        float4 B0 = b4[0], B1 = b4[1], B2 = b4[2];
        float bl[12] = {B0.x, B0.y, B0.z, B0.w, B1.x, B1.y, B1.z, B1.w,
                        B2.x, B2.y, B2.z, B2.w};
        // mid[m] = stage-A output at global index 8j+m, m = 0..11
        float mid[12];
#pragma unroll
        for (int sgl = 0; sgl < 6; sgl++) {
            // m = 2*sgl (even, w = 4j+sgl) and m = 2*sgl+1 (odd)
            mid[2 * sgl]     = fmaf(a0, bl[sgl],     fmaf(a1, bl[sgl + 1], fmaf(a2, bl[sgl + 2], a3 * bl[sgl + 3])));
            mid[2 * sgl + 1] = fmaf(p0, bl[sgl + 1], fmaf(p1, bl[sgl + 2], fmaf(p2, bl[sgl + 3], p3 * bl[sgl + 4])));
        }
        // final pairs u = 8j + t, t = 0..7; local mid index t
        float r[16];
#pragma unroll
        for (int t = 0; t < 8; t++) {
            r[2 * t]     = fmaf(e0, mid[t],     fmaf(e1, mid[t + 1], fmaf(e2, mid[t + 2], e3 * mid[t + 3])));
            r[2 * t + 1] = fmaf(o0, mid[t + 1], fmaf(o1, mid[t + 2], fmaf(o2, mid[t + 3], o3 * mid[t + 4])));
        }
        float4* o4 = reinterpret_cast<float4*>(outg + 16 * j);
#pragma unroll
        for (int q = 0; q < 4; q++)
            o4[q] = make_float4(r[4 * q], r[4 * q + 1], r[4 * q + 2], r[4 * q + 3]);
    }
}

__global__ void __launch_bounds__(NT, 3)
dwt_frontend_kernel(const float* __restrict__ x, float* __restrict__ out) {
    extern __shared__ float s[];
    const int tid = threadIdx.x;
    const int row = blockIdx.x;
    const float* xg = x + (size_t)row * LEN0;

    // ---- P0: load row (float4) ----
    {
        const float4* xg4 = reinterpret_cast<const float4*>(xg);
        float4* X4 = reinterpret_cast<float4*>(s + OFF_X);
        for (int i = tid; i < LEN0 / 4; i += NT) X4[i] = xg4[i];
    }
    __syncthreads();

    const size_t bstride = (size_t)gridDim.x * LEN0;
    float* ob = out + (size_t)row * LEN0;

    // ---- P1: analysis level 1 ----
    analysis_step(s + OFF_X, LEN0, s + OFF_A1, s + OFF_D1, LEN1, tid);
    __syncthreads();

    // ---- P2: analysis level 2  +  band3 (REC_HI(D1) -> gmem) ----
    analysis_step(s + OFF_A1, LEN1, s + OFF_A2, s + OFF_D2, LEN2, tid);
    synth_step(s + OFF_D1, LEN1, c_hi_e, c_hi_o, ob + 3 * bstride, tid);
    __syncthreads();

    // ---- P3: analysis level 3  +  band2 (hi then lo, fused, D2 -> gmem) ----
    analysis_step(s + OFF_A2, LEN2, s + OFF_A3, s + OFF_D3, LEN3, tid);
    synth2_fused(s + OFF_D2, LEN2, c_hi_e, c_hi_o, c_lo_e, c_lo_o, ob + 2 * bstride, tid);
    __syncthreads();

    // ---- P4: first synthesis stage of bands 1 and 0 (1031 -> 2054, smem) ----
    synth_step(s + OFF_D3, LEN3, c_hi_e, c_hi_o, s + OFF_B1_1, tid);
    synth_step(s + OFF_A3, LEN3, c_lo_e, c_lo_o, s + OFF_B0_1, tid);
    __syncthreads();

    // ---- P5: fused double synthesis of bands 1 and 0 -> gmem ----
    synth2_fused(s + OFF_B1_1, LEN2, c_lo_e, c_lo_o, c_lo_e, c_lo_o, ob + 1 * bstride, tid);
    synth2_fused(s + OFF_B0_1, LEN2, c_lo_e, c_lo_o, c_lo_e, c_lo_o, ob, tid);
}

extern "C" void kernel_launch(void* const* d_in, const int* in_sizes, int n_in,
                              void* d_out, int out_size) {
    const float* x = (const float*)d_in[0];
    float* out = (float*)d_out;
    const size_t smem = (size_t)ARENA * sizeof(float);   // 65568 B -> 3 CTAs/SM
    cudaFuncSetAttribute(dwt_frontend_kernel,
                         cudaFuncAttributeMaxDynamicSharedMemorySize, (int)smem);
    dwt_frontend_kernel<<<2048, NT, smem>>>(x, out);
}

// round 10
// speedup vs baseline: 1.0508x; 1.0508x over previous
#include <cuda_runtime.h>

// 3-level db4 wavelet front-end. One CTA per (b,c) row, 4 phases / 3 barriers.
// Ph1: analysis L1 straight from gmem. Ph2: analysis L2 + band3->gmem.
// Ph3: analysis L3 + band2 (double-fused synth)->gmem. Ph4: bands 1,0
// (triple-fused synth, registers only)->gmem. Flat-merged chunk lists per phase.

#define NT 512
#define LEN0 8192
#define LEN1 4100
#define LEN2 2054
#define LEN3 1031

// ---- smem arena (floats), 16B-aligned offsets ----
// Ph1 writes A1[0,4100) D1[4100,8200)
// Ph2 reads A1,D1; writes A2[8200,10256) D2[10256,12312)
// Ph3 reads A2,D2; writes A3[0,1032) D3[1032,2064)   (A1/D1 dead)
// Ph4 reads A3,D3; writes gmem only
#define OFF_A1 0
#define OFF_D1 4100
#define OFF_A2 8200
#define OFF_D2 10256
#define OFF_A3 0
#define OFF_D3 1032
#define ARENA  12312

__constant__ float c_dec_lo[8] = {
    -0.0105974018f, 0.0328830117f, 0.0308413818f, -0.1870348117f,
    -0.0279837694f, 0.6308807679f, 0.7148465706f, 0.2303778133f};
__constant__ float c_dec_hi[8] = {
    -0.2303778133f, 0.7148465706f, -0.6308807679f, -0.0279837694f,
     0.1870348117f, 0.0308413818f, -0.0328830117f, -0.0105974018f};

// Synthesis polyphase taps (transpose conv, crop 7, T = 2L-8):
//   out[2u]   = e0*a[u]   + e1*a[u+1] + e2*a[u+2] + e3*a[u+3]
//   out[2u+1] = o0*a[u+1] + o1*a[u+2] + o2*a[u+3] + o3*a[u+4]
__constant__ float c_lo_e[4] = {-0.0105974018f, 0.0308413818f, -0.0279837694f, 0.7148465706f};
__constant__ float c_lo_o[4] = { 0.0328830117f, -0.1870348117f, 0.6308807679f, 0.2303778133f};
__constant__ float c_hi_e[4] = {-0.2303778133f, -0.6308807679f, 0.1870348117f, -0.0328830117f};
__constant__ float c_hi_o[4] = { 0.7148465706f, -0.0279837694f, 0.0308413818f, -0.0105974018f};

// ---- analysis chunk (4 outputs) reading gmem directly; L=8192, Lout=4100 ----
__device__ __forceinline__ void analysis_chunk_g(const float* __restrict__ xg,
                                                 float* __restrict__ lo,
                                                 float* __restrict__ hi, int j) {
    if (j >= 1 && j <= 1023) {
        const float4* in4 = reinterpret_cast<const float4*>(xg) + (2 * j - 2);
        float v[16];
#pragma unroll
        for (int q = 0; q < 4; q++) {
            float4 t = in4[q];
            v[4 * q] = t.x; v[4 * q + 1] = t.y; v[4 * q + 2] = t.z; v[4 * q + 3] = t.w;
        }
        float slo[4], shi[4];
#pragma unroll
        for (int m = 0; m < 4; m++) {
            float sl = 0.f, sh = 0.f;
#pragma unroll
            for (int k = 0; k < 8; k++) {
                float xv = v[2 * m + 1 + k];
                sl = fmaf(xv, c_dec_lo[k], sl);
                sh = fmaf(xv, c_dec_hi[k], sh);
            }
            slo[m] = sl; shi[m] = sh;
        }
        *reinterpret_cast<float4*>(lo + 4 * j) = make_float4(slo[0], slo[1], slo[2], slo[3]);
        *reinterpret_cast<float4*>(hi + 4 * j) = make_float4(shi[0], shi[1], shi[2], shi[3]);
    } else {
#pragma unroll
        for (int m = 0; m < 4; m++) {
            int o = 4 * j + m;
            if (o >= LEN1) break;
            int base = 2 * o - 7;
            float sl = 0.f, sh = 0.f;
#pragma unroll
            for (int k = 0; k < 8; k++) {
                int i = base + k;
                i = i < 0 ? -i : i;
                i = min(i, 2 * LEN0 - 2 - i);
                float xv = xg[i];
                sl = fmaf(xv, c_dec_lo[k], sl);
                sh = fmaf(xv, c_dec_hi[k], sh);
            }
            lo[o] = sl;
            hi[o] = sh;
        }
    }
}

// ---- analysis chunk (4 outputs) from smem ----
__device__ __forceinline__ void analysis_chunk_s(const float* __restrict__ in, int L,
                                                 float* __restrict__ lo,
                                                 float* __restrict__ hi, int Lout, int j) {
    const int jhi = (L - 8) >> 3;
    if (j >= 1 && j <= jhi) {
        const float4* in4 = reinterpret_cast<const float4*>(in) + (2 * j - 2);
        float v[16];
#pragma unroll
        for (int q = 0; q < 4; q++) {
            float4 t = in4[q];
            v[4 * q] = t.x; v[4 * q + 1] = t.y; v[4 * q + 2] = t.z; v[4 * q + 3] = t.w;
        }
        float slo[4], shi[4];
#pragma unroll
        for (int m = 0; m < 4; m++) {
            float sl = 0.f, sh = 0.f;
#pragma unroll
            for (int k = 0; k < 8; k++) {
                float xv = v[2 * m + 1 + k];
                sl = fmaf(xv, c_dec_lo[k], sl);
                sh = fmaf(xv, c_dec_hi[k], sh);
            }
            slo[m] = sl; shi[m] = sh;
        }
        *reinterpret_cast<float4*>(lo + 4 * j) = make_float4(slo[0], slo[1], slo[2], slo[3]);
        *reinterpret_cast<float4*>(hi + 4 * j) = make_float4(shi[0], shi[1], shi[2], shi[3]);
    } else {
        const int twoLm2 = 2 * L - 2;
#pragma unroll
        for (int m = 0; m < 4; m++) {
            int o = 4 * j + m;
            if (o >= Lout) break;
            int base = 2 * o - 7;
            float sl = 0.f, sh = 0.f;
#pragma unroll
            for (int k = 0; k < 8; k++) {
                int i = base + k;
                i = i < 0 ? -i : i;
                i = min(i, twoLm2 - i);
                float xv = in[i];
                sl = fmaf(xv, c_dec_lo[k], sl);
                sh = fmaf(xv, c_dec_hi[k], sh);
            }
            lo[o] = sl;
            hi[o] = sh;
        }
    }
}

// ---- single-stage synth, 8 pairs/chunk; only for L=4100 (512 exact chunks) ----
__device__ __forceinline__ void synth8_chunk(const float* __restrict__ a,
                                             const float* __restrict__ wE,
                                             const float* __restrict__ wO,
                                             float* __restrict__ outg, int j) {
    const float e0 = wE[0], e1 = wE[1], e2 = wE[2], e3 = wE[3];
    const float o0 = wO[0], o1 = wO[1], o2 = wO[2], o3 = wO[3];
    const float4* a4 = reinterpret_cast<const float4*>(a + 8 * j);
    float4 A = a4[0], B = a4[1], C = a4[2];
    float v[12] = {A.x, A.y, A.z, A.w, B.x, B.y, B.z, B.w, C.x, C.y, C.z, C.w};
    float4* o4 = reinterpret_cast<float4*>(outg + 16 * j);
#pragma unroll
    for (int h = 0; h < 2; h++) {
        float r[8];
#pragma unroll
        for (int m = 0; m < 4; m++) {
            int t = 4 * h + m;
            r[2 * m]     = fmaf(e0, v[t],     fmaf(e1, v[t + 1], fmaf(e2, v[t + 2], e3 * v[t + 3])));
            r[2 * m + 1] = fmaf(o0, v[t + 1], fmaf(o1, v[t + 2], fmaf(o2, v[t + 3], o3 * v[t + 4])));
        }
        o4[2 * h]     = make_float4(r[0], r[1], r[2], r[3]);
        o4[2 * h + 1] = make_float4(r[4], r[5], r[6], r[7]);
    }
}

// ---- double-fused synth: b(2054) ->A-> 4100 ->lo-> 8192; 512 exact chunks ----
__device__ __forceinline__ void synth2_chunk(const float* __restrict__ b,
                                             const float* __restrict__ wAe,
                                             const float* __restrict__ wAo,
                                             float* __restrict__ outg, int j) {
    const float a0 = wAe[0], a1 = wAe[1], a2 = wAe[2], a3 = wAe[3];
    const float p0 = wAo[0], p1 = wAo[1], p2 = wAo[2], p3 = wAo[3];
    const float e0 = c_lo_e[0], e1 = c_lo_e[1], e2 = c_lo_e[2], e3 = c_lo_e[3];
    const float o0 = c_lo_o[0], o1 = c_lo_o[1], o2 = c_lo_o[2], o3 = c_lo_o[3];
    const float4* b4 = reinterpret_cast<const float4*>(b + 4 * j);
    float4 B0 = b4[0], B1 = b4[1], B2 = b4[2];
    float bl[12] = {B0.x, B0.y, B0.z, B0.w, B1.x, B1.y, B1.z, B1.w,
                    B2.x, B2.y, B2.z, B2.w};
    float mid[12];
#pragma unroll
    for (int g = 0; g < 6; g++) {
        mid[2 * g]     = fmaf(a0, bl[g],     fmaf(a1, bl[g + 1], fmaf(a2, bl[g + 2], a3 * bl[g + 3])));
        mid[2 * g + 1] = fmaf(p0, bl[g + 1], fmaf(p1, bl[g + 2], fmaf(p2, bl[g + 3], p3 * bl[g + 4])));
    }
    float4* o4 = reinterpret_cast<float4*>(outg + 16 * j);
#pragma unroll
    for (int h = 0; h < 2; h++) {
        float r[8];
#pragma unroll
        for (int m = 0; m < 4; m++) {
            int t = 4 * h + m;
            r[2 * m]     = fmaf(e0, mid[t],     fmaf(e1, mid[t + 1], fmaf(e2, mid[t + 2], e3 * mid[t + 3])));
            r[2 * m + 1] = fmaf(o0, mid[t + 1], fmaf(o1, mid[t + 2], fmaf(o2, mid[t + 3], o3 * mid[t + 4])));
        }
        o4[2 * h]     = make_float4(r[0], r[1], r[2], r[3]);
        o4[2 * h + 1] = make_float4(r[4], r[5], r[6], r[7]);
    }
}

// ---- triple-fused synth: b(1031) ->A-> 2054 ->lo-> 4100 ->lo-> 8192 ----
// 512 exact chunks; reads b[2j..2j+8] (+1 pad), writes out[16j..16j+15].
__device__ __forceinline__ void synth3_chunk(const float* __restrict__ b,
                                             const float* __restrict__ wAe,
                                             const float* __restrict__ wAo,
                                             float* __restrict__ outg, int j) {
    const float a0 = wAe[0], a1 = wAe[1], a2 = wAe[2], a3 = wAe[3];
    const float p0 = wAo[0], p1 = wAo[1], p2 = wAo[2], p3 = wAo[3];
    const float e0 = c_lo_e[0], e1 = c_lo_e[1], e2 = c_lo_e[2], e3 = c_lo_e[3];
    const float o0 = c_lo_o[0], o1 = c_lo_o[1], o2 = c_lo_o[2], o3 = c_lo_o[3];
    float bl[10];
    const float2* b2 = reinterpret_cast<const float2*>(b) + j;   // b + 2j
#pragma unroll
    for (int q = 0; q < 5; q++) { float2 t = b2[q]; bl[2 * q] = t.x; bl[2 * q + 1] = t.y; }
    // stage A: m1 local n = global(4j+n), n = 0..9
    float m1[10];
#pragma unroll
    for (int v = 0; v < 5; v++) {
        m1[2 * v]     = fmaf(a0, bl[v],     fmaf(a1, bl[v + 1], fmaf(a2, bl[v + 2], a3 * bl[v + 3])));
        m1[2 * v + 1] = fmaf(p0, bl[v + 1], fmaf(p1, bl[v + 2], fmaf(p2, bl[v + 3], p3 * bl[v + 4])));
    }
    // stage B (lo): m2 local m = global(8j+m), m = 0..11
    float m2[12];
#pragma unroll
    for (int w = 0; w < 6; w++) {
        m2[2 * w]     = fmaf(e0, m1[w],     fmaf(e1, m1[w + 1], fmaf(e2, m1[w + 2], e3 * m1[w + 3])));
        m2[2 * w + 1] = fmaf(o0, m1[w + 1], fmaf(o1, m1[w + 2], fmaf(o2, m1[w + 3], o3 * m1[w + 4])));
    }
    // stage C (lo): out[16j + 0..15]
    float4* o4 = reinterpret_cast<float4*>(outg + 16 * j);
#pragma unroll
    for (int h = 0; h < 2; h++) {
        float r[8];
#pragma unroll
        for (int m = 0; m < 4; m++) {
            int t = 4 * h + m;
            r[2 * m]     = fmaf(e0, m2[t],     fmaf(e1, m2[t + 1], fmaf(e2, m2[t + 2], e3 * m2[t + 3])));
            r[2 * m + 1] = fmaf(o0, m2[t + 1], fmaf(o1, m2[t + 2], fmaf(o2, m2[t + 3], o3 * m2[t + 4])));
        }
        o4[2 * h]     = make_float4(r[0], r[1], r[2], r[3]);
        o4[2 * h + 1] = make_float4(r[4], r[5], r[6], r[7]);
    }
}

__global__ void __launch_bounds__(NT, 3)
dwt_frontend_kernel(const float* __restrict__ x, float* __restrict__ out) {
    extern __shared__ float s[];
    const int tid = threadIdx.x;
    const int row = blockIdx.x;
    const float* xg = x + (size_t)row * LEN0;
    const size_t bstride = (size_t)gridDim.x * LEN0;
    float* ob = out + (size_t)row * LEN0;

    // ---- Ph1: analysis L1 straight from gmem (1025 chunks) ----
    for (int c = tid; c < 1025; c += NT)
        analysis_chunk_g(xg, s + OFF_A1, s + OFF_D1, c);
    __syncthreads();

    // ---- Ph2: analysis L2 (514) + band3 synth (512) = 1026 chunks ----
    for (int c = tid; c < 1026; c += NT) {
        if (c < 514)
            analysis_chunk_s(s + OFF_A1, LEN1, s + OFF_A2, s + OFF_D2, LEN2, c);
        else
            synth8_chunk(s + OFF_D1, c_hi_e, c_hi_o, ob + 3 * bstride, c - 514);
    }
    __syncthreads();

    // ---- Ph3: analysis L3 (258) + band2 double-fused synth (512) = 770 ----
    for (int c = tid; c < 770; c += NT) {
        if (c < 258)
            analysis_chunk_s(s + OFF_A2, LEN2, s + OFF_A3, s + OFF_D3, LEN3, c);
        else
            synth2_chunk(s + OFF_D2, c_hi_e, c_hi_o, ob + 2 * bstride, c - 258);
    }
    __syncthreads();

    // ---- Ph4: bands 1 and 0, triple-fused synth (512 + 512 = 1024) ----
    for (int c = tid; c < 1024; c += NT) {
        if (c < 512)
            synth3_chunk(s + OFF_D3, c_hi_e, c_hi_o, ob + 1 * bstride, c);
        else
            synth3_chunk(s + OFF_A3, c_lo_e, c_lo_o, ob, c - 512);
    }
}

extern "C" void kernel_launch(void* const* d_in, const int* in_sizes, int n_in,
                              void* d_out, int out_size) {
    const float* x = (const float*)d_in[0];
    float* out = (float*)d_out;
    const size_t smem = (size_t)ARENA * sizeof(float);   // 49248 B -> 3 CTAs/SM
    cudaFuncSetAttribute(dwt_frontend_kernel,
                         cudaFuncAttributeMaxDynamicSharedMemorySize, (int)smem);
    dwt_frontend_kernel<<<2048, NT, smem>>>(x, out);
}